// round 10
// baseline (speedup 1.0000x reference)
#include <cuda_runtime.h>
#include <cuda_bf16.h>
#include <cstdint>

#define N_NODES   4000000
#define N_GRAPHS  4096
#define D_FEAT    8
#define N_CLASSES 10
#define WARPS_PER_BLOCK 4
#define N_BLOCKS (N_GRAPHS / WARPS_PER_BLOCK)   // 1024
#define FULL 0xFFFFFFFFu

#define CHUNK_F4   256                           // float4 per chunk = 4 KB
#define CHUNK_B    (CHUNK_F4 * 16)
#define SMEM_DATA  (WARPS_PER_BLOCK * 2 * CHUNK_B)       // 32 KB
#define SMEM_MBAR  (SMEM_DATA)                            // mbar region offset
#define SMEM_TOTAL (SMEM_DATA + WARPS_PER_BLOCK * 2 * 8 + 16)

// batch_ids may be int64 OR int32 (JAX under default x64=False silently makes
// them int32). Values < 4096, so for int64 data every high word is 0.
__device__ __forceinline__ int id_at(const int* __restrict__ ids32, bool is64, int i) {
    return is64 ? ids32[2 * i] : ids32[i];
}

__device__ __forceinline__ int kary_lower_bound(
    const int* __restrict__ ids32, bool is64, int v,
    int lo, int hi, int sub, int half_shift)
{
    const unsigned hmask = 0xFFFFu << half_shift;
    while (hi - lo > 16) {
        const int range = hi - lo;
        const int pos = lo + (int)(((long long)range * (sub + 1)) >> 4);
        const bool less = id_at(ids32, is64, pos - 1) < v;
        const unsigned ball = __ballot_sync(hmask, less);
        const int cnt = __popc((ball >> half_shift) & 0xFFFFu);
        const int nlo = lo + (int)(((long long)range * cnt) >> 4);
        const int nhi = (cnt == 16) ? hi
                      : lo + (int)(((long long)range * (cnt + 1)) >> 4);
        lo = nlo; hi = nhi;
    }
    const int pos = lo + sub;
    const bool less = (pos < hi) ? (id_at(ids32, is64, pos) < v) : false;
    const unsigned ball = __ballot_sync(hmask, less);
    return lo + __popc((ball >> half_shift) & 0xFFFFu);
}

__device__ __forceinline__ uint32_t smem_u32(const void* p) {
    return (uint32_t)__cvta_generic_to_shared(p);
}

__device__ __forceinline__ void mbar_init(uint32_t mbar, uint32_t count) {
    asm volatile("mbarrier.init.shared.b64 [%0], %1;" :: "r"(mbar), "r"(count) : "memory");
}
__device__ __forceinline__ void bulk_issue(uint32_t dst, const void* src,
                                           uint32_t bytes, uint32_t mbar) {
    asm volatile("mbarrier.arrive.expect_tx.shared.b64 _, [%0], %1;"
                 :: "r"(mbar), "r"(bytes) : "memory");
    asm volatile("cp.async.bulk.shared::cta.global.mbarrier::complete_tx::bytes "
                 "[%0], [%1], %2, [%3];"
                 :: "r"(dst), "l"(src), "r"(bytes), "r"(mbar) : "memory");
}
__device__ __forceinline__ void mbar_wait(uint32_t mbar, uint32_t parity) {
    uint32_t done;
    do {
        asm volatile(
            "{\n\t.reg .pred p;\n\t"
            "mbarrier.try_wait.parity.acquire.cta.shared::cta.b64 p, [%1], %2;\n\t"
            "selp.b32 %0, 1, 0, p;\n\t}"
            : "=r"(done) : "r"(mbar), "r"(parity) : "memory");
    } while (!done);
}

__global__ __launch_bounds__(128) void fused_pool_gemm_kernel(
    const float4* __restrict__ x4,
    const int*    __restrict__ ids32,
    const float*  __restrict__ W,      // [10, 8]
    const float*  __restrict__ b,      // [10]
    float*        __restrict__ out)    // [4096, 10]
{
    extern __shared__ char smem[];
    const int warp = threadIdx.x >> 5;
    const int lane = threadIdx.x & 31;
    const int g    = blockIdx.x * WARPS_PER_BLOCK + warp;   // segment id

    const uint32_t sbase = smem_u32(smem);
    const uint32_t buf[2]  = { sbase + (uint32_t)(warp * 2    ) * CHUNK_B,
                               sbase + (uint32_t)(warp * 2 + 1) * CHUNK_B };
    const uint32_t mbar[2] = { sbase + SMEM_MBAR + (uint32_t)(warp * 2    ) * 8,
                               sbase + SMEM_MBAR + (uint32_t)(warp * 2 + 1) * 8 };
    if (lane == 0) { mbar_init(mbar[0], 1); mbar_init(mbar[1], 1); }
    asm volatile("fence.proxy.async.shared::cta;" ::: "memory");
    __syncwarp(FULL);

    // ---- Phase 1: per-warp cooperative boundary search ----
    const bool is64 = (ids32[N_NODES - 1] == 0);
    const int half_shift = lane & 16;
    const int sub = lane & 15;
    const int v = (half_shift == 0) ? g : g + 1;

    int res;
    if (v >= N_GRAPHS) {
        res = N_NODES;
    } else {
        const long long approx = ((long long)v * N_NODES) >> 12;
        int lo = (int)(approx - 8192); if (lo < 0) lo = 0;
        int hi = (int)(approx + 8192); if (hi > N_NODES) hi = N_NODES;
        const bool ok_lo = (lo == 0)       || (id_at(ids32, is64, lo - 1) < v);
        const bool ok_hi = (hi == N_NODES) || (id_at(ids32, is64, hi) >= v);
        if (!(ok_lo && ok_hi)) { lo = 0; hi = N_NODES; }
        res = kary_lower_bound(ids32, is64, v, lo, hi, sub, half_shift);
    }
    __syncwarp(FULL);
    const int start = __shfl_sync(FULL, res, 0);
    const int end   = __shfl_sync(FULL, res, 16);
    const int cnt   = end - start;
    const long long base = (long long)start * 2;   // float4 units
    const int n4 = cnt * 2;
    const int nch = (n4 + CHUNK_F4 - 1) / CHUNK_F4;

    // ---- Phase 2: double-buffered cp.async.bulk stream through smem ----
    if (lane == 0) {
        if (nch > 0) {
            const int sz0 = (n4 < CHUNK_F4 ? n4 : CHUNK_F4) * 16;
            bulk_issue(buf[0], (const char*)(x4 + base), sz0, mbar[0]);
        }
        if (nch > 1) {
            const int rem = n4 - CHUNK_F4;
            const int sz1 = (rem < CHUNK_F4 ? rem : CHUNK_F4) * 16;
            bulk_issue(buf[1], (const char*)(x4 + base + CHUNK_F4), sz1, mbar[1]);
        }
    }
    __syncwarp(FULL);

    float4 a0 = make_float4(0.f,0.f,0.f,0.f);
    float4 a1 = make_float4(0.f,0.f,0.f,0.f);
    int phase[2] = {0, 0};

    for (int k = 0; k < nch; k++) {
        const int bi = k & 1;
        mbar_wait(mbar[bi], phase[bi]);
        phase[bi] ^= 1;

        const int coff = k * CHUNK_F4;
        const int csz  = (n4 - coff < CHUNK_F4) ? (n4 - coff) : CHUNK_F4;
        const float4* cbuf = (const float4*)(smem + (size_t)(buf[bi] - sbase));

        if (csz == CHUNK_F4) {
            #pragma unroll
            for (int j = 0; j < CHUNK_F4 / 64; j++) {   // 4 pairs of LDS.128
                float4 v0 = cbuf[lane + j * 64];
                float4 v1 = cbuf[lane + j * 64 + 32];
                a0.x += v0.x; a0.y += v0.y; a0.z += v0.z; a0.w += v0.w;
                a1.x += v1.x; a1.y += v1.y; a1.z += v1.z; a1.w += v1.w;
            }
        } else {
            for (int j = lane; j < csz; j += 32) {
                float4 vv = cbuf[j];
                a0.x += vv.x; a0.y += vv.y; a0.z += vv.z; a0.w += vv.w;
            }
        }
        __syncwarp(FULL);
        if (lane == 0 && k + 2 < nch) {
            const int noff = (k + 2) * CHUNK_F4;
            const int nsz  = ((n4 - noff < CHUNK_F4) ? (n4 - noff) : CHUNK_F4) * 16;
            bulk_issue(buf[bi], (const char*)(x4 + base + noff), nsz, mbar[bi]);
        }
        __syncwarp(FULL);
    }
    a0.x += a1.x; a0.y += a1.y; a0.z += a1.z; a0.w += a1.w;

    // Parity-preserving butterfly: lane 0 -> cols 0-3, lane 1 -> cols 4-7.
    #pragma unroll
    for (int m = 16; m >= 2; m >>= 1) {
        a0.x += __shfl_xor_sync(FULL, a0.x, m);
        a0.y += __shfl_xor_sync(FULL, a0.y, m);
        a0.z += __shfl_xor_sync(FULL, a0.z, m);
        a0.w += __shfl_xor_sync(FULL, a0.w, m);
    }

    // ---- Phase 3: broadcast pooled vector, fused tiny GEMM ----
    const float inv = (cnt > 0) ? (1.0f / (float)cnt) : 0.0f;
    const float p0 = __shfl_sync(FULL, a0.x, 0) * inv;
    const float p1 = __shfl_sync(FULL, a0.y, 0) * inv;
    const float p2 = __shfl_sync(FULL, a0.z, 0) * inv;
    const float p3 = __shfl_sync(FULL, a0.w, 0) * inv;
    const float p4 = __shfl_sync(FULL, a0.x, 1) * inv;
    const float p5 = __shfl_sync(FULL, a0.y, 1) * inv;
    const float p6 = __shfl_sync(FULL, a0.z, 1) * inv;
    const float p7 = __shfl_sync(FULL, a0.w, 1) * inv;

    if (lane < N_CLASSES) {
        const float* w = W + lane * D_FEAT;
        float r = __ldg(&b[lane]);
        r += p0 * __ldg(&w[0]) + p1 * __ldg(&w[1]) + p2 * __ldg(&w[2]) + p3 * __ldg(&w[3]);
        r += p4 * __ldg(&w[4]) + p5 * __ldg(&w[5]) + p6 * __ldg(&w[6]) + p7 * __ldg(&w[7]);
        out[g * N_CLASSES + lane] = r;
    }
}

extern "C" void kernel_launch(void* const* d_in, const int* in_sizes, int n_in,
                              void* d_out, int out_size) {
    const float* x   = nullptr;
    const void*  ids = nullptr;
    const float* W   = nullptr;
    const float* b   = nullptr;
    for (int i = 0; i < n_in; i++) {
        switch (in_sizes[i]) {
            case N_NODES * D_FEAT:   x   = (const float*)d_in[i]; break;
            case N_NODES:            ids = d_in[i];               break;
            case N_CLASSES * D_FEAT: W   = (const float*)d_in[i]; break;
            case N_CLASSES:          b   = (const float*)d_in[i]; break;
            default: break; // input_ids / attention_mask: unused
        }
    }
    float* out = (float*)d_out;

    static bool attr_done = false;
    if (!attr_done) {
        cudaFuncSetAttribute(fused_pool_gemm_kernel,
                             cudaFuncAttributeMaxDynamicSharedMemorySize, SMEM_TOTAL);
        attr_done = true;
    }

    fused_pool_gemm_kernel<<<N_BLOCKS, 128, SMEM_TOTAL>>>(
        (const float4*)x, (const int*)ids, W, b, out);
}

// round 11
// speedup vs baseline: 1.1110x; 1.1110x over previous
#include <cuda_runtime.h>
#include <cuda_bf16.h>
#include <cstdint>

#define N_NODES   4000000
#define N_GRAPHS  4096
#define D_FEAT    8
#define N_CLASSES 10
#define WARPS_PER_BLOCK 4
#define N_BLOCKS (N_GRAPHS / WARPS_PER_BLOCK)   // 1024
#define FULL 0xFFFFFFFFu

#define STAGE_F4  128                 // float4 per stage = 2 KB
#define STAGE_B   (STAGE_F4 * 16)
#define STAGES    3
#define WSMEM     (STAGES * STAGE_B)  // 6 KB per warp
#define BSMEM     (WARPS_PER_BLOCK * WSMEM)   // 24 KB per block (static)

// batch_ids may be int64 OR int32 (JAX under default x64=False silently makes
// them int32). Values < 4096, so for int64 data every high word is 0: viewing
// the buffer as int32, element N_NODES-1 is an int64 high word (==0) or the
// max sorted int32 id (>0).
__device__ __forceinline__ int id_at(const int* __restrict__ ids32, bool is64, int i) {
    return is64 ? ids32[2 * i] : ids32[i];
}

// Half-warp cooperative 16-ary lower_bound of v over sorted ids in [lo, hi).
__device__ __forceinline__ int kary_lower_bound(
    const int* __restrict__ ids32, bool is64, int v,
    int lo, int hi, int sub, int half_shift)
{
    const unsigned hmask = 0xFFFFu << half_shift;
    while (hi - lo > 16) {
        const int range = hi - lo;
        const int pos = lo + (int)(((long long)range * (sub + 1)) >> 4);
        const bool less = id_at(ids32, is64, pos - 1) < v;
        const unsigned ball = __ballot_sync(hmask, less);
        const int cnt = __popc((ball >> half_shift) & 0xFFFFu);
        const int nlo = lo + (int)(((long long)range * cnt) >> 4);
        const int nhi = (cnt == 16) ? hi
                      : lo + (int)(((long long)range * (cnt + 1)) >> 4);
        lo = nlo; hi = nhi;
    }
    const int pos = lo + sub;
    const bool less = (pos < hi) ? (id_at(ids32, is64, pos) < v) : false;
    const unsigned ball = __ballot_sync(hmask, less);
    return lo + __popc((ball >> half_shift) & 0xFFFFu);
}

// Issue one 2KB stage: each lane copies 4x16B via cp.async (no dest regs!).
__device__ __forceinline__ void issue_stage(
    uint32_t dst_u32, const float4* __restrict__ src_g,
    int soff, int n4, int lane)
{
    #pragma unroll
    for (int t = 0; t < 4; t++) {
        const int j = soff + lane + t * 32;
        if (j < n4) {
            const uint32_t d = dst_u32 + (uint32_t)(lane + t * 32) * 16;
            asm volatile("cp.async.cg.shared.global [%0], [%1], 16;"
                         :: "r"(d), "l"((const void*)(src_g + j)) : "memory");
        }
    }
}

__global__ __launch_bounds__(128) void fused_pool_gemm_kernel(
    const float4* __restrict__ x4,
    const int*    __restrict__ ids32,
    const float*  __restrict__ W,      // [10, 8]
    const float*  __restrict__ b,      // [10]
    float*        __restrict__ out)    // [4096, 10]
{
    __shared__ __align__(16) char smem[BSMEM];

    const int warp = threadIdx.x >> 5;
    const int lane = threadIdx.x & 31;
    const int g    = blockIdx.x * WARPS_PER_BLOCK + warp;   // segment id

    char* wsmem = smem + warp * WSMEM;
    const uint32_t wsmem_u32 = (uint32_t)__cvta_generic_to_shared(wsmem);

    // ---- Phase 1: per-warp cooperative boundary search ----
    const bool is64 = (ids32[N_NODES - 1] == 0);
    const int half_shift = lane & 16;
    const int sub = lane & 15;
    const int v = (half_shift == 0) ? g : g + 1;   // lower half: start; upper: end

    int res;
    if (v >= N_GRAPHS) {
        res = N_NODES;
    } else {
        // +-8192 window (>=8 sd of binomial start position); bracket-verified
        // with full-range fallback.
        const long long approx = ((long long)v * N_NODES) >> 12;
        int lo = (int)(approx - 8192); if (lo < 0) lo = 0;
        int hi = (int)(approx + 8192); if (hi > N_NODES) hi = N_NODES;
        const bool ok_lo = (lo == 0)       || (id_at(ids32, is64, lo - 1) < v);
        const bool ok_hi = (hi == N_NODES) || (id_at(ids32, is64, hi) >= v);
        if (!(ok_lo && ok_hi)) { lo = 0; hi = N_NODES; }
        res = kary_lower_bound(ids32, is64, v, lo, hi, sub, half_shift);
    }
    __syncwarp(FULL);
    const int start = __shfl_sync(FULL, res, 0);
    const int end   = __shfl_sync(FULL, res, 16);
    const int cnt   = end - start;
    const float4* seg = x4 + (long long)start * 2;
    const int n4 = cnt * 2;
    const int nst = (n4 + STAGE_F4 - 1) / STAGE_F4;

    // ---- Phase 2: 3-stage cp.async pipeline through shared memory ----
    // Each lane copies and later reads ONLY its own 4 float4 slots per stage,
    // so per-thread wait_group ordering suffices (no cross-lane smem deps).
    #pragma unroll
    for (int s = 0; s < STAGES; s++) {
        if (s < nst)
            issue_stage(wsmem_u32 + s * STAGE_B, seg, s * STAGE_F4, n4, lane);
        asm volatile("cp.async.commit_group;" ::: "memory");
    }

    float4 a0 = make_float4(0.f,0.f,0.f,0.f);
    float4 a1 = make_float4(0.f,0.f,0.f,0.f);

    for (int k = 0; k < nst; k++) {
        asm volatile("cp.async.wait_group 2;" ::: "memory");   // stage k landed

        const float4* cbuf = (const float4*)(wsmem + (k % STAGES) * STAGE_B);
        const int soff = k * STAGE_F4;
        if (soff + STAGE_F4 <= n4) {
            float4 v0 = cbuf[lane     ];
            float4 v1 = cbuf[lane + 32];
            float4 v2 = cbuf[lane + 64];
            float4 v3 = cbuf[lane + 96];
            a0.x += v0.x; a0.y += v0.y; a0.z += v0.z; a0.w += v0.w;
            a1.x += v1.x; a1.y += v1.y; a1.z += v1.z; a1.w += v1.w;
            a0.x += v2.x; a0.y += v2.y; a0.z += v2.z; a0.w += v2.w;
            a1.x += v3.x; a1.y += v3.y; a1.z += v3.z; a1.w += v3.w;
        } else {
            #pragma unroll
            for (int t = 0; t < 4; t++) {
                const int j = soff + lane + t * 32;
                if (j < n4) {
                    float4 vv = cbuf[lane + t * 32];
                    a0.x += vv.x; a0.y += vv.y; a0.z += vv.z; a0.w += vv.w;
                }
            }
        }
        // refill the buffer just consumed with stage k+STAGES
        if (k + STAGES < nst)
            issue_stage(wsmem_u32 + (k % STAGES) * STAGE_B, seg,
                        (k + STAGES) * STAGE_F4, n4, lane);
        asm volatile("cp.async.commit_group;" ::: "memory");
    }
    asm volatile("cp.async.wait_group 0;" ::: "memory");
    a0.x += a1.x; a0.y += a1.y; a0.z += a1.z; a0.w += a1.w;

    // Parity-preserving butterfly: lane 0 -> cols 0-3, lane 1 -> cols 4-7.
    #pragma unroll
    for (int m = 16; m >= 2; m >>= 1) {
        a0.x += __shfl_xor_sync(FULL, a0.x, m);
        a0.y += __shfl_xor_sync(FULL, a0.y, m);
        a0.z += __shfl_xor_sync(FULL, a0.z, m);
        a0.w += __shfl_xor_sync(FULL, a0.w, m);
    }

    // ---- Phase 3: broadcast pooled vector via shuffles, fused tiny GEMM ----
    const float inv = (cnt > 0) ? (1.0f / (float)cnt) : 0.0f;
    const float p0 = __shfl_sync(FULL, a0.x, 0) * inv;
    const float p1 = __shfl_sync(FULL, a0.y, 0) * inv;
    const float p2 = __shfl_sync(FULL, a0.z, 0) * inv;
    const float p3 = __shfl_sync(FULL, a0.w, 0) * inv;
    const float p4 = __shfl_sync(FULL, a0.x, 1) * inv;
    const float p5 = __shfl_sync(FULL, a0.y, 1) * inv;
    const float p6 = __shfl_sync(FULL, a0.z, 1) * inv;
    const float p7 = __shfl_sync(FULL, a0.w, 1) * inv;

    if (lane < N_CLASSES) {
        const float* w = W + lane * D_FEAT;
        float r = __ldg(&b[lane]);
        r += p0 * __ldg(&w[0]) + p1 * __ldg(&w[1]) + p2 * __ldg(&w[2]) + p3 * __ldg(&w[3]);
        r += p4 * __ldg(&w[4]) + p5 * __ldg(&w[5]) + p6 * __ldg(&w[6]) + p7 * __ldg(&w[7]);
        out[g * N_CLASSES + lane] = r;
    }
}

extern "C" void kernel_launch(void* const* d_in, const int* in_sizes, int n_in,
                              void* d_out, int out_size) {
    // Bind inputs by element count (robust to metadata ordering):
    //   x: 32,000,000 f32 | batch_ids: 4,000,000 | W: 80 | b: 10
    const float* x   = nullptr;
    const void*  ids = nullptr;
    const float* W   = nullptr;
    const float* b   = nullptr;
    for (int i = 0; i < n_in; i++) {
        switch (in_sizes[i]) {
            case N_NODES * D_FEAT:   x   = (const float*)d_in[i]; break;
            case N_NODES:            ids = d_in[i];               break;
            case N_CLASSES * D_FEAT: W   = (const float*)d_in[i]; break;
            case N_CLASSES:          b   = (const float*)d_in[i]; break;
            default: break; // input_ids / attention_mask: unused
        }
    }
    float* out = (float*)d_out;

    fused_pool_gemm_kernel<<<N_BLOCKS, 128>>>(
        (const float4*)x, (const int*)ids, W, b, out);
}